// round 10
// baseline (speedup 1.0000x reference)
#include <cuda_runtime.h>
#include <cuda_bf16.h>
#include <math.h>

#define NTOK 4096
#define EDIM 1024
#define NH   16
#define HD   32
#define NL   6

typedef __nv_bfloat16 bf16;

// ---------------- scratch (device globals; no allocs allowed) ----------------
__device__ float g_z  [NTOK * EDIM];
__device__ float g_tmp[NTOK * EDIM];
__device__ float g_an [NTOK * EDIM];
__device__ float g_qkv[NTOK * 1536];

__device__ __align__(16) bf16 g_z_hi [NTOK * EDIM],     g_z_mid [NTOK * EDIM];
__device__ __align__(16) bf16 g_an_hi[NTOK * EDIM],     g_an_mid[NTOK * EDIM];
__device__ __align__(16) bf16 g_ff_hi[NTOK * 2 * EDIM], g_ff_mid[NTOK * 2 * EDIM];
__device__ __align__(16) bf16 g_o_hi [NTOK * 512],      g_o_mid [NTOK * 512];
__device__ __align__(16) bf16 g_qkv_hi[NTOK * 1536],    g_qkv_mid[NTOK * 1536];

__device__ __align__(16) bf16 g_wqkv_hi[NL * 1536 * 1024], g_wqkv_mid[NL * 1536 * 1024];
__device__ __align__(16) bf16 g_wo_hi  [NL * 1024 * 512],  g_wo_mid  [NL * 1024 * 512];
__device__ __align__(16) bf16 g_w1_hi  [NL * 2048 * 1024], g_w1_mid  [NL * 2048 * 1024];
__device__ __align__(16) bf16 g_w2_hi  [NL * 1024 * 2048], g_w2_mid  [NL * 1024 * 2048];

// ---------------- helpers ----------------
__device__ __forceinline__ unsigned pack2(bf16 lo, bf16 hi) {
    return (unsigned)__bfloat16_as_ushort(lo) | ((unsigned)__bfloat16_as_ushort(hi) << 16);
}
__device__ __forceinline__ void split2(float x0, float x1, unsigned& whi, unsigned& wmid) {
    bf16 h0 = __float2bfloat16_rn(x0), h1 = __float2bfloat16_rn(x1);
    bf16 m0 = __float2bfloat16_rn(x0 - __bfloat162float(h0));
    bf16 m1 = __float2bfloat16_rn(x1 - __bfloat162float(h1));
    whi = pack2(h0, h1); wmid = pack2(m0, m1);
}
__device__ __forceinline__ void mma_bf16(float* d, const unsigned* a, unsigned b0, unsigned b1) {
    asm volatile(
        "mma.sync.aligned.m16n8k16.row.col.f32.bf16.bf16.f32 "
        "{%0,%1,%2,%3},{%4,%5,%6,%7},{%8,%9},{%0,%1,%2,%3};"
        : "+f"(d[0]), "+f"(d[1]), "+f"(d[2]), "+f"(d[3])
        : "r"(a[0]), "r"(a[1]), "r"(a[2]), "r"(a[3]), "r"(b0), "r"(b1));
}
__device__ __forceinline__ void ldsm4(unsigned* r, unsigned addr) {
    asm volatile("ldmatrix.sync.aligned.m8n8.x4.shared.b16 {%0,%1,%2,%3},[%4];"
        : "=r"(r[0]), "=r"(r[1]), "=r"(r[2]), "=r"(r[3]) : "r"(addr));
}
__device__ __forceinline__ void cpasync16(void* dst, const void* src) {
    unsigned d = (unsigned)__cvta_generic_to_shared(dst);
    asm volatile("cp.async.cg.shared.global [%0],[%1],16;" :: "r"(d), "l"(src) : "memory");
}
#define CP_COMMIT() asm volatile("cp.async.commit_group;" ::: "memory")
#define CP_WAIT0()  asm volatile("cp.async.wait_group 0;" ::: "memory")
#define CP_WAIT1()  asm volatile("cp.async.wait_group 1;" ::: "memory")

// 64B rows as 4x16B chunks; physical chunk = c ^ ((r>>1)&3)
__device__ __forceinline__ int swz(int r, int c) { return r * 4 + (c ^ ((r >> 1) & 3)); }

// ---------------- embedding (+ split planes) ----------------
__global__ void embed_kernel(const int* __restrict__ ctx,
                             const float* __restrict__ table,
                             const float* __restrict__ pos) {
    int n = blockIdx.x, i = threadIdx.x;
    int tok = ctx[n];
    float4 a = ((const float4*)(table + (size_t)tok * EDIM))[i];
    float4 b = ((const float4*)(pos + (size_t)n * EDIM))[i];
    float4 v = make_float4(a.x + b.x, a.y + b.y, a.z + b.z, a.w + b.w);
    ((float4*)(g_z + (size_t)n * EDIM))[i] = v;
    unsigned h0, m0, h1, m1;
    split2(v.x, v.y, h0, m0); split2(v.z, v.w, h1, m1);
    unsigned* zh = (unsigned*)(g_z_hi + (size_t)n * EDIM);
    unsigned* zm = (unsigned*)(g_z_mid + (size_t)n * EDIM);
    zh[i * 2] = h0; zh[i * 2 + 1] = h1;
    zm[i * 2] = m0; zm[i * 2 + 1] = m1;
}

// ---------------- transpose+split: in[R][C] -> out[C][R] hi/mid, per blockIdx.z slab ----------------
__global__ void tsplit_kernel(const float* __restrict__ in, bf16* __restrict__ ohi,
                              bf16* __restrict__ omid, int R, int C) {
    size_t bs = (size_t)R * C * blockIdx.z;
    in += bs; ohi += bs; omid += bs;
    __shared__ float tile[32][33];
    int c0 = blockIdx.x * 32, r0 = blockIdx.y * 32;
    int tx = threadIdx.x, ty = threadIdx.y;
    #pragma unroll
    for (int i = 0; i < 4; i++)
        tile[ty + 8 * i][tx] = in[(size_t)(r0 + ty + 8 * i) * C + c0 + tx];
    __syncthreads();
    #pragma unroll
    for (int i = 0; i < 4; i++) {
        float v = tile[tx][ty + 8 * i];
        size_t o = (size_t)(c0 + ty + 8 * i) * R + r0 + tx;
        bf16 h = __float2bfloat16_rn(v);
        ohi[o] = h;
        omid[o] = __float2bfloat16_rn(v - __bfloat162float(h));
    }
}

// ---------------- qkv weight transpose+split: W[l][h][e][v] -> [l][sel*512+h*32+v][e] ----------------
__global__ void qkv_split_kernel(const float* __restrict__ Wq,
                                 const float* __restrict__ Wk,
                                 const float* __restrict__ Wv) {
    int lh = blockIdx.y;
    int l = lh >> 4, h = lh & 15;
    int r0 = blockIdx.x * 32;
    int tx = threadIdx.x, ty = threadIdx.y;
    __shared__ float tile[32][33];
    const float* Ws[3] = {Wq, Wk, Wv};
    for (int sel = 0; sel < 3; sel++) {
        const float* in = Ws[sel] + (size_t)lh * (EDIM * HD);
        #pragma unroll
        for (int i = 0; i < 4; i++)
            tile[ty + 8 * i][tx] = in[(size_t)(r0 + ty + 8 * i) * 32 + tx];
        __syncthreads();
        size_t base = ((size_t)l * 1536 + sel * 512 + h * 32) * 1024;
        #pragma unroll
        for (int i = 0; i < 4; i++) {
            float v = tile[tx][ty + 8 * i];
            size_t o = base + (size_t)(ty + 8 * i) * 1024 + r0 + tx;
            bf16 hh = __float2bfloat16_rn(v);
            g_wqkv_hi[o] = hh;
            g_wqkv_mid[o] = __float2bfloat16_rn(v - __bfloat162float(hh));
        }
        __syncthreads();
    }
}

// ---------------- bf16x3 mma GEMM v3: C[M,N] = A[M,K] @ B[N,K]^T ----------------
// 64x64 block, BK=32, 128 thr (2Mx2N warps, warp tile 32x32). STATIC 32KB smem.
// EPI: 0 = C fp32 + planes; 1 = bias+leaky planes only; 2 = bias+res C; 3 = res C.
template<int EPI>
__global__ __launch_bounds__(128)
void gemm_kernel(const bf16* __restrict__ Ahi, const bf16* __restrict__ Amid,
                 const bf16* __restrict__ Bhi, const bf16* __restrict__ Bmid,
                 const float* __restrict__ bias, const float* __restrict__ res,
                 float* __restrict__ C, bf16* __restrict__ Chi, bf16* __restrict__ Cmid,
                 int N, int K) {
    __shared__ __align__(16) char sm[2 * 16384];   // [buf][Ahi 4K|Amid 4K|Bhi 4K|Bmid 4K]
    const int t = threadIdx.x, lane = t & 31, wid = t >> 5;
    const int g = lane >> 2, qq = lane & 3;
    const int m0 = (wid & 1) * 32, n0 = (wid >> 1) * 32;
    const int by = blockIdx.y * 64, bx = blockIdx.x * 64;
    const unsigned smb = (unsigned)__cvta_generic_to_shared(sm);
    const bf16* Apl[2] = {Ahi, Amid};
    const bf16* Bpl[2] = {Bhi, Bmid};

    float acc[2][4][4];
    #pragma unroll
    for (int i = 0; i < 2; i++)
        #pragma unroll
        for (int j = 0; j < 4; j++)
            #pragma unroll
            for (int c = 0; c < 4; c++) acc[i][j][c] = 0.f;

    const int KT = K >> 5;

    auto stage = [&](int kt) {
        int buf = kt & 1, k0 = kt * 32;
        char* base = sm + buf * 16384;
        #pragma unroll
        for (int i = 0; i < 8; i++) {
            int gi = i * 128 + t;             // 0..1023
            int arr = (gi >> 8) & 1;          // plane hi/mid
            int wdx = gi & 255;
            int r = wdx >> 2, c = wdx & 3;
            if (gi < 512)
                cpasync16(base + arr * 4096 + swz(r, c) * 16,
                          Apl[arr] + (size_t)(by + r) * K + k0 + c * 8);
            else
                cpasync16(base + 8192 + arr * 4096 + swz(r, c) * 16,
                          Bpl[arr] + (size_t)(bx + r) * K + k0 + c * 8);
        }
        CP_COMMIT();
    };

    auto compute = [&](int kt) {
        int buf = kt & 1;
        unsigned b0 = smb + buf * 16384;
        unsigned ah = b0, am = b0 + 4096, bhp = b0 + 8192, bmp = b0 + 12288;
        #pragma unroll
        for (int s = 0; s < 2; s++) {
            unsigned af[2][2][4];
            #pragma unroll
            for (int mt = 0; mt < 2; mt++) {
                int row = m0 + mt * 16 + (lane & 15);
                int c = 2 * s + (lane >> 4);
                ldsm4(af[0][mt], ah + swz(row, c) * 16);
                ldsm4(af[1][mt], am + swz(row, c) * 16);
            }
            #pragma unroll
            for (int pr = 0; pr < 2; pr++) {
                int mm = lane >> 3;
                int row = n0 + pr * 16 + (mm >> 1) * 8 + (lane & 7);
                int c = 2 * s + (mm & 1);
                unsigned bh[4], bm[4];
                ldsm4(bh, bhp + swz(row, c) * 16);
                ldsm4(bm, bmp + swz(row, c) * 16);
                #pragma unroll
                for (int sub = 0; sub < 2; sub++) {
                    int nt = pr * 2 + sub;
                    #pragma unroll
                    for (int mt = 0; mt < 2; mt++) {
                        mma_bf16(acc[mt][nt], af[0][mt], bh[sub * 2], bh[sub * 2 + 1]);
                        mma_bf16(acc[mt][nt], af[0][mt], bm[sub * 2], bm[sub * 2 + 1]);
                        mma_bf16(acc[mt][nt], af[1][mt], bh[sub * 2], bh[sub * 2 + 1]);
                    }
                }
            }
        }
    };

    stage(0);
    for (int kt = 0; kt < KT; kt++) {
        if (kt + 1 < KT) { stage(kt + 1); CP_WAIT1(); }
        else { CP_WAIT0(); }
        __syncthreads();
        compute(kt);
        __syncthreads();
    }

    #pragma unroll
    for (int mt = 0; mt < 2; mt++)
        #pragma unroll
        for (int rr = 0; rr < 2; rr++) {
            int row = by + m0 + mt * 16 + g + rr * 8;
            #pragma unroll
            for (int nt = 0; nt < 4; nt++) {
                int col = bx + n0 + nt * 8 + qq * 2;
                float v0 = acc[mt][nt][rr * 2 + 0];
                float v1 = acc[mt][nt][rr * 2 + 1];
                if (EPI == 1 || EPI == 2) {
                    float2 bv = *(const float2*)&bias[col];
                    v0 += bv.x; v1 += bv.y;
                }
                if (EPI == 1) {
                    v0 = (v0 > 0.f) ? v0 : 0.01f * v0;
                    v1 = (v1 > 0.f) ? v1 : 0.01f * v1;
                }
                if (EPI == 2 || EPI == 3) {
                    float2 rv = *(const float2*)&res[(size_t)row * N + col];
                    v0 += rv.x; v1 += rv.y;
                }
                size_t o = (size_t)row * N + col;
                if (EPI != 1) *(float2*)&C[o] = make_float2(v0, v1);
                if (EPI == 0 || EPI == 1) {
                    unsigned wh, wm;
                    split2(v0, v1, wh, wm);
                    *(unsigned*)&Chi[o] = wh;
                    *(unsigned*)&Cmid[o] = wm;
                }
            }
        }
}

// ---------------- flash attention (SIMT fp32, KNOWN GOOD) + plane epilogue ----------------
// grid (NTOK/128, NH), block 128. One query row per thread. Reads g_qkv [n][1536].
__global__ __launch_bounds__(128)
void attn_kernel() {
    __shared__ float Ks[32][32];
    __shared__ float Vs[32][32];
    int h = blockIdx.y;
    int qrow = blockIdx.x * 128 + threadIdx.x;
    const float scale = 0.17677669529663687f;   // 1/sqrt(32)

    float q[32], o[32];
    const float* qp = g_qkv + (size_t)qrow * 1536 + h * 32;
    #pragma unroll
    for (int v4 = 0; v4 < 8; v4++) {
        float4 t4 = *(const float4*)&qp[v4 * 4];
        q[v4 * 4 + 0] = t4.x * scale; q[v4 * 4 + 1] = t4.y * scale;
        q[v4 * 4 + 2] = t4.z * scale; q[v4 * 4 + 3] = t4.w * scale;
    }
    #pragma unroll
    for (int v = 0; v < 32; v++) o[v] = 0.f;
    float m = -1e30f, l = 0.f;

    const float* kbase = g_qkv + 512 + h * 32;
    const float* vbase = g_qkv + 1024 + h * 32;
    int t = threadIdx.x;

    for (int kb = 0; kb < NTOK; kb += 32) {
        #pragma unroll
        for (int j = 0; j < 2; j++) {
            int idx = t + j * 128;
            int r = idx >> 3, c4 = idx & 7;
            *(float4*)&Ks[r][c4 * 4] = *(const float4*)&kbase[(size_t)(kb + r) * 1536 + c4 * 4];
            *(float4*)&Vs[r][c4 * 4] = *(const float4*)&vbase[(size_t)(kb + r) * 1536 + c4 * 4];
        }
        __syncthreads();

        float s[32];
        float mloc = -1e30f;
        #pragma unroll
        for (int j = 0; j < 32; j++) {
            float acc = 0.f;
            #pragma unroll
            for (int v4 = 0; v4 < 8; v4++) {
                float4 kk = *(float4*)&Ks[j][v4 * 4];
                acc += q[v4 * 4 + 0] * kk.x + q[v4 * 4 + 1] * kk.y
                     + q[v4 * 4 + 2] * kk.z + q[v4 * 4 + 3] * kk.w;
            }
            s[j] = acc;
            mloc = fmaxf(mloc, acc);
        }
        float mnew = fmaxf(m, mloc);
        float alpha = __expf(m - mnew);
        float psum = 0.f;
        #pragma unroll
        for (int j = 0; j < 32; j++) {
            s[j] = __expf(s[j] - mnew);
            psum += s[j];
        }
        l = l * alpha + psum;
        #pragma unroll
        for (int v = 0; v < 32; v++) o[v] *= alpha;
        #pragma unroll
        for (int j = 0; j < 32; j++) {
            float p = s[j];
            #pragma unroll
            for (int v4 = 0; v4 < 8; v4++) {
                float4 vv = *(float4*)&Vs[j][v4 * 4];
                o[v4 * 4 + 0] += p * vv.x; o[v4 * 4 + 1] += p * vv.y;
                o[v4 * 4 + 2] += p * vv.z; o[v4 * 4 + 3] += p * vv.w;
            }
        }
        m = mnew;
        __syncthreads();
    }

    // epilogue: normalize + write bf16 hi/mid planes [n][512]
    float inv = 1.f / l;
    size_t base = (size_t)qrow * 512 + h * 32;
    #pragma unroll
    for (int j = 0; j < 16; j++) {
        unsigned wh, wm;
        split2(o[2 * j] * inv, o[2 * j + 1] * inv, wh, wm);
        *(unsigned*)&g_o_hi [base + 2 * j] = wh;
        *(unsigned*)&g_o_mid[base + 2 * j] = wm;
    }
}

// ---------------- row LayerNorm (ddof=1, no eps) + optional plane split ----------------
template<int PL>
__global__ __launch_bounds__(256)
void ln_kernel(const float* __restrict__ in, float* __restrict__ out,
               bf16* __restrict__ ohi, bf16* __restrict__ omid) {
    int n = blockIdx.x;
    const float* x = in + (size_t)n * EDIM;
    float xv[4], s1 = 0.f, s2 = 0.f;
    #pragma unroll
    for (int i = 0; i < 4; i++) {
        float v = x[threadIdx.x + i * 256];
        xv[i] = v; s1 += v; s2 += v * v;
    }
    #pragma unroll
    for (int off = 16; off; off >>= 1) {
        s1 += __shfl_down_sync(0xffffffffu, s1, off);
        s2 += __shfl_down_sync(0xffffffffu, s2, off);
    }
    __shared__ float r1[8], r2[8];
    __shared__ float mean_s, inv_s;
    int w = threadIdx.x >> 5;
    if ((threadIdx.x & 31) == 0) { r1[w] = s1; r2[w] = s2; }
    __syncthreads();
    if (threadIdx.x == 0) {
        float a = 0.f, b = 0.f;
        #pragma unroll
        for (int i = 0; i < 8; i++) { a += r1[i]; b += r2[i]; }
        float mean = a / (float)EDIM;
        mean_s = mean;
        inv_s = rsqrtf((b - (float)EDIM * mean * mean) / (float)(EDIM - 1));
    }
    __syncthreads();
    float mean = mean_s, inv = inv_s;
    #pragma unroll
    for (int i = 0; i < 4; i++) {
        size_t o = (size_t)n * EDIM + threadIdx.x + i * 256;
        float y = (xv[i] - mean) * inv;
        out[o] = y;
        if (PL) {
            bf16 h = __float2bfloat16_rn(y);
            ohi[o] = h;
            omid[o] = __float2bfloat16_rn(y - __bfloat162float(h));
        }
    }
}

// ---------------- host orchestration ----------------
extern "C" void kernel_launch(void* const* d_in, const int* in_sizes, int n_in,
                              void* d_out, int out_size) {
    const int*   ctx   = (const int*)  d_in[0];
    const float* table = (const float*)d_in[1];
    const float* pos   = (const float*)d_in[2];
    const float* Wq    = (const float*)d_in[3];
    const float* Wk    = (const float*)d_in[4];
    const float* Wv    = (const float*)d_in[5];
    const float* Wo    = (const float*)d_in[6];
    const float* W1    = (const float*)d_in[7];
    const float* b1    = (const float*)d_in[8];
    const float* W2    = (const float*)d_in[9];
    const float* b2    = (const float*)d_in[10];

    float *z, *tmp, *an, *qkv;
    bf16 *z_hi, *z_mid, *an_hi, *an_mid, *ff_hi, *ff_mid, *o_hi, *o_mid, *qkv_hi, *qkv_mid;
    bf16 *wqkv_hi, *wqkv_mid, *wo_hi, *wo_mid, *w1_hi, *w1_mid, *w2_hi, *w2_mid;
    cudaGetSymbolAddress((void**)&z,   g_z);
    cudaGetSymbolAddress((void**)&tmp, g_tmp);
    cudaGetSymbolAddress((void**)&an,  g_an);
    cudaGetSymbolAddress((void**)&qkv, g_qkv);
    cudaGetSymbolAddress((void**)&z_hi,  g_z_hi);   cudaGetSymbolAddress((void**)&z_mid,  g_z_mid);
    cudaGetSymbolAddress((void**)&an_hi, g_an_hi);  cudaGetSymbolAddress((void**)&an_mid, g_an_mid);
    cudaGetSymbolAddress((void**)&ff_hi, g_ff_hi);  cudaGetSymbolAddress((void**)&ff_mid, g_ff_mid);
    cudaGetSymbolAddress((void**)&o_hi,  g_o_hi);   cudaGetSymbolAddress((void**)&o_mid,  g_o_mid);
    cudaGetSymbolAddress((void**)&qkv_hi, g_qkv_hi); cudaGetSymbolAddress((void**)&qkv_mid, g_qkv_mid);
    cudaGetSymbolAddress((void**)&wqkv_hi, g_wqkv_hi); cudaGetSymbolAddress((void**)&wqkv_mid, g_wqkv_mid);
    cudaGetSymbolAddress((void**)&wo_hi, g_wo_hi);  cudaGetSymbolAddress((void**)&wo_mid, g_wo_mid);
    cudaGetSymbolAddress((void**)&w1_hi, g_w1_hi);  cudaGetSymbolAddress((void**)&w1_mid, g_w1_mid);
    cudaGetSymbolAddress((void**)&w2_hi, g_w2_hi);  cudaGetSymbolAddress((void**)&w2_mid, g_w2_mid);

    dim3 tb(32, 8);
    embed_kernel<<<NTOK, 256>>>(ctx, table, pos);
    qkv_split_kernel<<<dim3(EDIM / 32, NL * NH), tb>>>(Wq, Wk, Wv);
    tsplit_kernel<<<dim3(32, 16, NL), tb>>>(Wo, wo_hi, wo_mid, 512, 1024);
    tsplit_kernel<<<dim3(64, 32, NL), tb>>>(W1, w1_hi, w1_mid, 1024, 2048);
    tsplit_kernel<<<dim3(32, 64, NL), tb>>>(W2, w2_hi, w2_mid, 2048, 1024);

    for (int l = 0; l < NL; l++) {
        const bf16* wqh = wqkv_hi + (size_t)l * 1536 * 1024;
        const bf16* wqm = wqkv_mid + (size_t)l * 1536 * 1024;
        const bf16* woh = wo_hi + (size_t)l * 1024 * 512;
        const bf16* wom = wo_mid + (size_t)l * 1024 * 512;
        const bf16* w1h = w1_hi + (size_t)l * 2048 * 1024;
        const bf16* w1m = w1_mid + (size_t)l * 2048 * 1024;
        const bf16* w2h = w2_hi + (size_t)l * 1024 * 2048;
        const bf16* w2m = w2_mid + (size_t)l * 1024 * 2048;
        const float* bb1 = b1 + (size_t)l * 2 * EDIM;
        const float* bb2 = b2 + (size_t)l * EDIM;

        // qkv = z @ Wqkv^T : fp32 + planes
        gemm_kernel<0><<<dim3(1536 / 64, NTOK / 64), 128>>>(
            z_hi, z_mid, wqh, wqm, nullptr, nullptr, qkv, qkv_hi, qkv_mid, 1536, 1024);

        attn_kernel<<<dim3(NTOK / 128, NH), 128>>>();

        // tmp = z + o @ Wo^T
        gemm_kernel<3><<<dim3(1024 / 64, NTOK / 64), 128>>>(
            o_hi, o_mid, woh, wom, nullptr, z, tmp, nullptr, nullptr, 1024, 512);
        ln_kernel<1><<<NTOK, 256>>>(tmp, an, an_hi, an_mid);

        // ff = leaky(an @ W1^T + b1) : planes only
        gemm_kernel<1><<<dim3(2048 / 64, NTOK / 64), 128>>>(
            an_hi, an_mid, w1h, w1m, bb1, nullptr, nullptr, ff_hi, ff_mid, 2048, 1024);

        // tmp = an + ff @ W2^T + b2
        gemm_kernel<2><<<dim3(1024 / 64, NTOK / 64), 128>>>(
            ff_hi, ff_mid, w2h, w2m, bb2, an, tmp, nullptr, nullptr, 1024, 2048);

        if (l == NL - 1)
            ln_kernel<0><<<NTOK, 256>>>(tmp, (float*)d_out, nullptr, nullptr);
        else
            ln_kernel<1><<<NTOK, 256>>>(tmp, z, z_hi, z_mid);
    }
}

// round 12
// speedup vs baseline: 1.1756x; 1.1756x over previous
#include <cuda_runtime.h>
#include <math.h>

#define NTOK 4096
#define EDIM 1024
#define NH   16
#define HD   32
#define NL   6

typedef unsigned long long u64;

// ---------------- scratch (device globals; no allocs allowed) ----------------
__device__ float g_z  [NTOK * EDIM];        // 16 MB
__device__ float g_tmp[NTOK * EDIM];        // 16 MB
__device__ float g_an [NTOK * EDIM];        // 16 MB
__device__ float g_qkv[NTOK * 1536];        // [n][1536]: q | k | v
__device__ float g_o  [NTOK * NH * HD];     // [n][h*32+v]
__device__ float g_ff [NTOK * 2 * EDIM];    // 32 MB
__device__ float g_wt [NL * EDIM * 1536];   // transposed QKV weights [l][e][c]

// ---------------- packed f32x2 helpers ----------------
__device__ __forceinline__ u64 ffma2(u64 a, u64 b, u64 c) {
    u64 r;
    asm("fma.rn.f32x2 %0, %1, %2, %3;" : "=l"(r) : "l"(a), "l"(b), "l"(c));
    return r;
}
__device__ __forceinline__ u64 fmul2(u64 a, u64 b) {
    u64 r;
    asm("mul.rn.f32x2 %0, %1, %2;" : "=l"(r) : "l"(a), "l"(b));
    return r;
}
__device__ __forceinline__ u64 packff(float x, float y) {
    u64 r;
    asm("mov.b64 %0, {%1, %2};" : "=l"(r) : "f"(x), "f"(y));
    return r;
}
__device__ __forceinline__ float2 unpackff(u64 v) {
    float2 f;
    asm("mov.b64 {%0, %1}, %2;" : "=f"(f.x), "=f"(f.y) : "l"(v));
    return f;
}
__device__ __forceinline__ void cpasync16(void* dst, const void* src) {
    unsigned d = (unsigned)__cvta_generic_to_shared(dst);
    asm volatile("cp.async.cg.shared.global [%0],[%1],16;" :: "r"(d), "l"(src) : "memory");
}
#define CP_COMMIT() asm volatile("cp.async.commit_group;" ::: "memory")
#define CP_WAIT0()  asm volatile("cp.async.wait_group 0;" ::: "memory")
#define CP_WAIT1()  asm volatile("cp.async.wait_group 1;" ::: "memory")

// ---------------- embedding: z = table[ctx] + pos ----------------
__global__ void embed_kernel(const int* __restrict__ ctx,
                             const float* __restrict__ table,
                             const float* __restrict__ pos) {
    int n = blockIdx.x, i = threadIdx.x;
    int tok = ctx[n];
    float4 a = ((const float4*)(table + (size_t)tok * EDIM))[i];
    float4 b = ((const float4*)(pos + (size_t)n * EDIM))[i];
    ((float4*)(g_z + (size_t)n * EDIM))[i] =
        make_float4(a.x + b.x, a.y + b.y, a.z + b.z, a.w + b.w);
}

// ---------------- weight transpose: g_wt[l][e][c], c = sel*512 + h*32 + v ----------------
__global__ void wt_kernel(const float* __restrict__ Wq,
                          const float* __restrict__ Wk,
                          const float* __restrict__ Wv) {
    int e = blockIdx.x;
    int l = blockIdx.y;
    #pragma unroll
    for (int i = 0; i < 6; i++) {
        int c = threadIdx.x + i * 256;          // 0..1535
        int sel = c >> 9;
        int hv  = c & 511;
        const float* W = (sel == 0) ? Wq : (sel == 1) ? Wk : Wv;
        g_wt[((size_t)l * EDIM + e) * 1536 + c] =
            W[(size_t)l * 524288 + (size_t)(hv >> 5) * 32768 + (size_t)e * 32 + (hv & 31)];
    }
}

// ---------------- f32x2 SIMT GEMM: C[M,N] = A[M,K] @ B[K,N] ----------------
// 128x64 block tile, BK=16, 128 threads, 8x8 microtile (pairs along N via f32x2).
// cp.async double-buffered, 24KB static smem.
// EPI: 0 none (qkv); 1 bias+leaky (ff1); 2 bias+res (ff2); 3 res (oproj)
template<int EPI>
__global__ __launch_bounds__(128)
void f2gemm_kernel(const float* __restrict__ A, const float* __restrict__ B,
                   const float* __restrict__ bias, const float* __restrict__ res,
                   float* __restrict__ C, int N, int K) {
    __shared__ __align__(16) float As[2][128 * 16];   // [m][k]
    __shared__ __align__(16) float Bs[2][16 * 64];    // [k][n]
    const int t = threadIdx.x;
    const int tx = t & 7;            // 8 col-groups of 8
    const int ty8 = (t >> 3) * 8;    // 16 row-groups of 8
    const int by = blockIdx.y * 128, bx = blockIdx.x * 64;

    u64 acc[8][4];
    #pragma unroll
    for (int i = 0; i < 8; i++)
        #pragma unroll
        for (int j = 0; j < 4; j++) acc[i][j] = 0ull;

    const int KT = K >> 4;

    auto stage = [&](int kt) {
        int buf = kt & 1, k0 = kt * 16;
        #pragma unroll
        for (int i = 0; i < 4; i++) {           // A: 128 rows x 4 chunks
            int gi = i * 128 + t;
            int r = gi >> 2, c = gi & 3;
            cpasync16(&As[buf][r * 16 + c * 4], A + (size_t)(by + r) * K + k0 + c * 4);
        }
        #pragma unroll
        for (int i = 0; i < 2; i++) {           // B: 16 rows x 16 chunks
            int gi = i * 128 + t;
            int r = gi >> 4, c = gi & 15;
            cpasync16(&Bs[buf][r * 64 + c * 4], B + (size_t)(k0 + r) * N + bx + c * 4);
        }
        CP_COMMIT();
    };

    auto compute = [&](int kt) {
        int buf = kt & 1;
        const float* Ab = &As[buf][ty8 * 16];
        const float* Bb = &Bs[buf][tx * 8];
        #pragma unroll
        for (int k = 0; k < 16; k++) {
            u64 bd[4];
            const u64* bp = (const u64*)(Bb + k * 64);
            #pragma unroll
            for (int j = 0; j < 4; j++) bd[j] = bp[j];
            #pragma unroll
            for (int i = 0; i < 8; i++) {
                float a = Ab[i * 16 + k];
                u64 ad = packff(a, a);
                #pragma unroll
                for (int j = 0; j < 4; j++)
                    acc[i][j] = ffma2(ad, bd[j], acc[i][j]);
            }
        }
    };

    stage(0);
    for (int kt = 0; kt < KT; kt++) {
        if (kt + 1 < KT) { stage(kt + 1); CP_WAIT1(); }
        else { CP_WAIT0(); }
        __syncthreads();
        compute(kt);
        __syncthreads();
    }

    // epilogue
    #pragma unroll
    for (int i = 0; i < 8; i++) {
        int row = by + ty8 + i;
        #pragma unroll
        for (int j = 0; j < 4; j++) {
            int col = bx + tx * 8 + j * 2;
            float2 v = unpackff(acc[i][j]);
            if (EPI == 1 || EPI == 2) {
                float2 bv = *(const float2*)&bias[col];
                v.x += bv.x; v.y += bv.y;
            }
            if (EPI == 1) {
                v.x = (v.x > 0.f) ? v.x : 0.01f * v.x;
                v.y = (v.y > 0.f) ? v.y : 0.01f * v.y;
            }
            if (EPI == 2 || EPI == 3) {
                float2 rv = *(const float2*)&res[(size_t)row * N + col];
                v.x += rv.x; v.y += rv.y;
            }
            *(float2*)&C[(size_t)row * N + col] = v;
        }
    }
}

// ---------------- flash attention (SIMT, f32x2 inner loops) ----------------
// grid (NTOK/128, NH), block 128. One query row per thread. Reads g_qkv [n][1536].
__global__ __launch_bounds__(128)
void attn_kernel() {
    __shared__ __align__(16) float Ks[32][32];
    __shared__ __align__(16) float Vs[32][32];
    int h = blockIdx.y;
    int qrow = blockIdx.x * 128 + threadIdx.x;
    const float scale = 0.17677669529663687f;   // 1/sqrt(32)

    u64 q2[16], o2[16];
    const float* qp = g_qkv + (size_t)qrow * 1536 + h * 32;
    #pragma unroll
    for (int v4 = 0; v4 < 8; v4++) {
        float4 t4 = *(const float4*)&qp[v4 * 4];
        q2[v4 * 2 + 0] = packff(t4.x * scale, t4.y * scale);
        q2[v4 * 2 + 1] = packff(t4.z * scale, t4.w * scale);
    }
    #pragma unroll
    for (int d = 0; d < 16; d++) o2[d] = 0ull;
    float m = -1e30f, l = 0.f;

    const float* kbase = g_qkv + 512 + h * 32;
    const float* vbase = g_qkv + 1024 + h * 32;
    int t = threadIdx.x;

    for (int kb = 0; kb < NTOK; kb += 32) {
        #pragma unroll
        for (int j = 0; j < 2; j++) {
            int idx = t + j * 128;
            int r = idx >> 3, c4 = idx & 7;
            *(float4*)&Ks[r][c4 * 4] = *(const float4*)&kbase[(size_t)(kb + r) * 1536 + c4 * 4];
            *(float4*)&Vs[r][c4 * 4] = *(const float4*)&vbase[(size_t)(kb + r) * 1536 + c4 * 4];
        }
        __syncthreads();

        float s[32];
        float mloc = -1e30f;
        #pragma unroll
        for (int j = 0; j < 32; j++) {
            u64 a0 = 0ull, a1 = 0ull;
            const ulonglong2* kk = (const ulonglong2*)Ks[j];
            #pragma unroll
            for (int v = 0; v < 8; v++) {
                ulonglong2 p2 = kk[v];
                a0 = ffma2(q2[2 * v], p2.x, a0);
                a1 = ffma2(q2[2 * v + 1], p2.y, a1);
            }
            float2 f0 = unpackff(a0), f1 = unpackff(a1);
            float acc = (f0.x + f0.y) + (f1.x + f1.y);
            s[j] = acc;
            mloc = fmaxf(mloc, acc);
        }
        float mnew = fmaxf(m, mloc);
        float alpha = __expf(m - mnew);
        float psum = 0.f;
        #pragma unroll
        for (int j = 0; j < 32; j++) {
            s[j] = __expf(s[j] - mnew);
            psum += s[j];
        }
        l = l * alpha + psum;
        u64 ad = packff(alpha, alpha);
        #pragma unroll
        for (int d = 0; d < 16; d++) o2[d] = fmul2(o2[d], ad);
        #pragma unroll
        for (int j = 0; j < 32; j++) {
            u64 pd = packff(s[j], s[j]);
            const ulonglong2* vv = (const ulonglong2*)Vs[j];
            #pragma unroll
            for (int v = 0; v < 8; v++) {
                ulonglong2 v2 = vv[v];
                o2[2 * v]     = ffma2(pd, v2.x, o2[2 * v]);
                o2[2 * v + 1] = ffma2(pd, v2.y, o2[2 * v + 1]);
            }
        }
        m = mnew;
        __syncthreads();
    }

    float inv = 1.f / l;
    float* op = g_o + (size_t)qrow * (NH * HD) + (size_t)h * HD;
    #pragma unroll
    for (int d = 0; d < 8; d++) {
        float2 a = unpackff(o2[2 * d]);
        float2 b = unpackff(o2[2 * d + 1]);
        *(float4*)&op[d * 4] = make_float4(a.x * inv, a.y * inv, b.x * inv, b.y * inv);
    }
}

// ---------------- row LayerNorm (ddof=1, no eps), E=1024, 256 threads ----------------
__global__ __launch_bounds__(256)
void ln_kernel(const float* __restrict__ in, float* __restrict__ out) {
    int n = blockIdx.x;
    const float* x = in + (size_t)n * EDIM;
    float xv[4], s1 = 0.f, s2 = 0.f;
    #pragma unroll
    for (int i = 0; i < 4; i++) {
        float v = x[threadIdx.x + i * 256];
        xv[i] = v; s1 += v; s2 += v * v;
    }
    #pragma unroll
    for (int off = 16; off; off >>= 1) {
        s1 += __shfl_down_sync(0xffffffffu, s1, off);
        s2 += __shfl_down_sync(0xffffffffu, s2, off);
    }
    __shared__ float r1[8], r2[8];
    __shared__ float mean_s, inv_s;
    int w = threadIdx.x >> 5;
    if ((threadIdx.x & 31) == 0) { r1[w] = s1; r2[w] = s2; }
    __syncthreads();
    if (threadIdx.x == 0) {
        float a = 0.f, b = 0.f;
        #pragma unroll
        for (int i = 0; i < 8; i++) { a += r1[i]; b += r2[i]; }
        float mean = a / (float)EDIM;
        mean_s = mean;
        inv_s = rsqrtf((b - (float)EDIM * mean * mean) / (float)(EDIM - 1));
    }
    __syncthreads();
    float mean = mean_s, inv = inv_s;
    #pragma unroll
    for (int i = 0; i < 4; i++)
        out[(size_t)n * EDIM + threadIdx.x + i * 256] = (xv[i] - mean) * inv;
}

// ---------------- host orchestration ----------------
extern "C" void kernel_launch(void* const* d_in, const int* in_sizes, int n_in,
                              void* d_out, int out_size) {
    const int*   ctx   = (const int*)  d_in[0];
    const float* table = (const float*)d_in[1];
    const float* pos   = (const float*)d_in[2];
    const float* Wq    = (const float*)d_in[3];
    const float* Wk    = (const float*)d_in[4];
    const float* Wv    = (const float*)d_in[5];
    const float* Wo    = (const float*)d_in[6];
    const float* W1    = (const float*)d_in[7];
    const float* b1    = (const float*)d_in[8];
    const float* W2    = (const float*)d_in[9];
    const float* b2    = (const float*)d_in[10];

    float *z, *tmp, *an, *qkv, *o, *ff, *wt;
    cudaGetSymbolAddress((void**)&z,   g_z);
    cudaGetSymbolAddress((void**)&tmp, g_tmp);
    cudaGetSymbolAddress((void**)&an,  g_an);
    cudaGetSymbolAddress((void**)&qkv, g_qkv);
    cudaGetSymbolAddress((void**)&o,   g_o);
    cudaGetSymbolAddress((void**)&ff,  g_ff);
    cudaGetSymbolAddress((void**)&wt,  g_wt);

    embed_kernel<<<NTOK, 256>>>(ctx, table, pos);
    wt_kernel<<<dim3(EDIM, NL), 256>>>(Wq, Wk, Wv);

    const size_t wo_stride = (size_t)NH * HD * EDIM;   // 524288
    const size_t w1_stride = (size_t)EDIM * 2 * EDIM;
    const size_t w2_stride = (size_t)2 * EDIM * EDIM;

    for (int l = 0; l < NL; l++) {
        const float* wtl = wt + (size_t)l * EDIM * 1536;
        const float* wo  = Wo + (size_t)l * wo_stride;
        const float* w1  = W1 + (size_t)l * w1_stride;
        const float* bb1 = b1 + (size_t)l * 2 * EDIM;
        const float* w2  = W2 + (size_t)l * w2_stride;
        const float* bb2 = b2 + (size_t)l * EDIM;

        // qkv = z @ Wt   [4096 x 1536], K=1024
        f2gemm_kernel<0><<<dim3(1536 / 64, NTOK / 128), 128>>>(
            z, wtl, nullptr, nullptr, qkv, 1536, EDIM);

        attn_kernel<<<dim3(NTOK / 128, NH), 128>>>();

        // tmp = z + o @ Wo   [4096 x 1024], K=512
        f2gemm_kernel<3><<<dim3(EDIM / 64, NTOK / 128), 128>>>(
            o, wo, nullptr, z, tmp, EDIM, NH * HD);
        ln_kernel<<<NTOK, 256>>>(tmp, an);

        // ff = leaky(an @ W1 + b1)   [4096 x 2048], K=1024
        f2gemm_kernel<1><<<dim3(2 * EDIM / 64, NTOK / 128), 128>>>(
            an, w1, bb1, nullptr, ff, 2 * EDIM, EDIM);

        // tmp = an + ff @ W2 + b2   [4096 x 1024], K=2048
        f2gemm_kernel<2><<<dim3(EDIM / 64, NTOK / 128), 128>>>(
            ff, w2, bb2, an, tmp, EDIM, 2 * EDIM);

        ln_kernel<<<NTOK, 256>>>(tmp, (l == NL - 1) ? (float*)d_out : z);
    }
}